// round 8
// baseline (speedup 1.0000x reference)
#include <cuda_runtime.h>
#include <cuda_bf16.h>
#include <cstdint>

#define B_    32
#define CIN   384
#define CHID  128
#define NCC   6
#define NTAPS 9
#define NCHUNK (NCC * NTAPS)   // 54
#define THREADS 256

// As layout: byte = srow*ROWB + col*128 + ((k8 ^ (col&7))<<4) + low8
#define ROWB     (66 * 128)               // 8448 bytes per halo row
#define AS_BYTES (4 * ROWB)               // 33792 (4 halo rows)

#define OFF_B1S 0
#define OFF_W2S 512
#define OFF_AS  1024
#define OFF_B   (OFF_AS + AS_BYTES)       // 34816; 4 buffers of 16384
#define SMEM_TOTAL (OFF_B + 4 * 16384)    // 100352

// W1 bf16 in mma-fragment order: [tap][cc][half][ks][jj][lane] x 16B
__device__ __align__(16) uint4 g_w1b[NTAPS * NCC * 2 * 4 * 4 * 32];

__device__ __forceinline__ uint32_t smem_u32(const void* p) {
    uint32_t a;
    asm("{ .reg .u64 t; cvta.to.shared.u64 t, %1; cvt.u32.u64 %0, t; }" : "=r"(a) : "l"(p));
    return a;
}
__device__ __forceinline__ uint32_t cvt2(float lo, float hi) {
    __nv_bfloat162 h = __float22bfloat162_rn(make_float2(lo, hi));
    return *reinterpret_cast<uint32_t*>(&h);
}
__device__ __forceinline__ void sts64(uint32_t a, uint32_t x, uint32_t y) {
    asm volatile("st.shared.v2.b32 [%0], {%1,%2};" :: "r"(a), "r"(x), "r"(y) : "memory");
}
__device__ __forceinline__ void sts128(uint32_t a, uint32_t x, uint32_t y, uint32_t z, uint32_t w) {
    asm volatile("st.shared.v4.b32 [%0], {%1,%2,%3,%4};" :: "r"(a), "r"(x), "r"(y), "r"(z), "r"(w) : "memory");
}
__device__ __forceinline__ void lds128(uint32_t* r, uint32_t a) {
    asm volatile("ld.shared.v4.b32 {%0,%1,%2,%3}, [%4];"
                 : "=r"(r[0]), "=r"(r[1]), "=r"(r[2]), "=r"(r[3]) : "r"(a));
}
__device__ __forceinline__ void ldmA(uint32_t* r, uint32_t a) {
    asm volatile("ldmatrix.sync.aligned.m8n8.x4.shared.b16 {%0,%1,%2,%3}, [%4];"
                 : "=r"(r[0]), "=r"(r[1]), "=r"(r[2]), "=r"(r[3]) : "r"(a));
}
__device__ __forceinline__ void mma_bf16(float* d, const uint32_t* a, uint32_t b0, uint32_t b1) {
    asm volatile("mma.sync.aligned.m16n8k16.row.col.f32.bf16.bf16.f32 "
                 "{%0,%1,%2,%3}, {%4,%5,%6,%7}, {%8,%9}, {%0,%1,%2,%3};"
                 : "+f"(d[0]), "+f"(d[1]), "+f"(d[2]), "+f"(d[3])
                 : "r"(a[0]), "r"(a[1]), "r"(a[2]), "r"(a[3]), "r"(b0), "r"(b1));
}

// ---- prep: W1 (HWIO fp32) -> g_w1b (bf16, mma-fragment order) ----
__global__ void prep_w1_kernel(const float* __restrict__ w1) {
    int u = blockIdx.x * 256 + threadIdx.x;          // 0..55295
    int lane = u & 31;  int r = u >> 5;
    int j    = r & 3;   r >>= 2;
    int ks   = r & 3;   r >>= 2;
    int half = r & 1;   r >>= 1;
    int cc   = r % NCC;
    int tap  = r / NCC;
    int g = lane >> 2, t = lane & 3;
    uint32_t wd[4];
    #pragma unroll
    for (int w = 0; w < 4; w++) {
        int nt = 2 * j + (w >> 1);
        int n  = half * 64 + nt * 8 + g;
        int kb = cc * 64 + ks * 16 + 2 * t + (w & 1) * 8;
        float f0 = w1[(size_t)(tap * CIN + kb) * CHID + n];
        float f1 = w1[(size_t)(tap * CIN + kb + 1) * CHID + n];
        wd[w] = cvt2(f0, f1);
    }
    g_w1b[u] = make_uint4(wd[0], wd[1], wd[2], wd[3]);
}

// 1-float4-per-thread A staging helpers (phase-sliced)
__device__ __forceinline__ float4 ldA1(const float* __restrict__ xb, int hin, int win,
                                       int tcc, int q) {
    if ((unsigned)hin < 64u)
        return *reinterpret_cast<const float4*>(xb + ((size_t)(hin * 64 + win)) * CIN + tcc * 64 + q * 4);
    return make_float4(0.f, 0.f, 0.f, 0.f);
}
__device__ __forceinline__ void stA1(uint32_t abase, int srow, int win, int q, float4 f) {
    const int sc = win + 1;
    const uint32_t addr = abase + srow * ROWB + sc * 128 +
                          (((q >> 1) ^ (sc & 7)) << 4) + (q & 1) * 8;
    sts64(addr, cvt2(f.x, f.y), cvt2(f.z, f.w));
}

__device__ __forceinline__ void stageB(uint32_t bbase, int chunk, int tid) {
    const uint4* src = g_w1b + (size_t)((chunk % NTAPS) * NCC + (chunk / NTAPS)) * 1024;
    #pragma unroll
    for (int i = 0; i < 4; i++) {
        int idx = i * THREADS + tid;
        size_t ga = (size_t)__cvta_generic_to_global(src + idx);
        asm volatile("cp.async.cg.shared.global [%0], [%1], 16;"
                     :: "r"(bbase + idx * 16), "l"(ga) : "memory");
    }
}

__global__ void __launch_bounds__(THREADS, 2)
kp_mma_kernel(const float* __restrict__ x,
              const float* __restrict__ b1,
              const float* __restrict__ w2,
              const float* __restrict__ b2,
              float* __restrict__ out)
{
    extern __shared__ char smem[];
    const uint32_t sb = smem_u32(smem);
    const int tid  = threadIdx.x;
    const int wid  = tid >> 5;
    const int lane = tid & 31;
    const int wm   = wid >> 2;      // 0..1: output row rp*2+wm
    const int wn   = wid & 3;       // 0..3: n-slice of 32
    const int g    = lane >> 2;
    const int t    = lane & 3;
    const int l15  = lane & 15;
    const int kh   = lane >> 4;     // ldmatrix k-half
    const int q15  = tid & 15;      // A-staging float4 slot (fixed per thread)
    const int w16  = tid >> 4;      // A-staging col base

    const int b  = blockIdx.x >> 5;
    const int rp = blockIdx.x & 31;
    const float* xb = x + (size_t)b * 64 * 64 * CIN;

    float* b1s = reinterpret_cast<float*>(smem + OFF_B1S);
    float* w2s = reinterpret_cast<float*>(smem + OFF_W2S);
    if (tid < CHID) { b1s[tid] = b1[tid]; w2s[tid] = w2[tid]; }

    // zero As once: halo columns (sc=0,65) and out-of-image rows stay 0
    #pragma unroll
    for (int i = 0; i < 9; i++) {
        const int idx = i * THREADS + tid;
        if (idx < AS_BYTES / 16)
            sts128(sb + OFF_AS + idx * 16, 0u, 0u, 0u, 0u);
    }

    // prologue: B chunks 0,1 as one group
    stageB(sb + OFF_B + 0 * 16384, 0, tid);
    stageB(sb + OFF_B + 1 * 16384, 1, tid);
    asm volatile("cp.async.commit_group;" ::: "memory");

    // prologue: stage srows 0,1 of cc=0 (srows 2,3 staged inside groups 0,1)
    #pragma unroll
    for (int s = 0; s < 2; s++) {
        const int hin = rp * 2 - 1 + s;
        #pragma unroll
        for (int ph = 0; ph < 4; ph++) {
            const int win = ph * 16 + w16;
            stA1(sb + OFF_AS, s, win, q15, ldA1(xb, hin, win, 0, q15));
        }
    }

    float acc[4][4][4];
    #pragma unroll
    for (int i = 0; i < 4; i++)
        #pragma unroll
        for (int nt = 0; nt < 4; nt++)
            #pragma unroll
            for (int c = 0; c < 4; c++) acc[i][nt][c] = 0.f;

    const uint32_t Bwn = (uint32_t)((wn >> 1) * 8192 + (wn & 1) * 1024);

    for (int cc = 0; cc < NCC; cc++) {
        #pragma unroll
        for (int grp = 0; grp < 5; grp++) {
            const int t0  = grp * 2;               // 0,2,4,6,8
            const int gsz = (grp == 4) ? 1 : 2;
            const int ch0 = cc * NTAPS + t0;

            asm volatile("cp.async.wait_group 0;" ::: "memory");
            __syncthreads();

            // stage next group's B chunks (1-deep lookahead, disjoint buffers mod 4)
            {
                const int ns = ch0 + gsz;
                if (ns < NCHUNK) {
                    stageB(sb + OFF_B + (uint32_t)(ns % 4) * 16384, ns, tid);
                    if (t0 != 6 && ns + 1 < NCHUNK)
                        stageB(sb + OFF_B + (uint32_t)((ns + 1) % 4) * 16384, ns + 1, tid);
                    asm volatile("cp.async.commit_group;" ::: "memory");
                }
            }

            // A-staging task for this group: grp0->srow2(cc), grp1->srow3(cc),
            // grp2->srow0(cc+1), grp3->srow1(cc+1), grp4->none.
            // Staged srow never overlaps srows read by this group's taps.
            const bool doA  = (grp < 2) || (grp < 4 && cc + 1 < NCC);
            const int  srow = (grp < 2) ? (grp + 2) : (grp - 2);
            const int  tcc  = (grp < 2) ? cc : cc + 1;
            const int  hinA = rp * 2 - 1 + srow;
            float4 fA; int winA = 0;

            #pragma unroll
            for (int u = 0; u < 2; u++) {
                if (u >= gsz) break;
                const int tap = t0 + u;
                const int ch  = ch0 + u;
                const int dy = tap / 3 - 1, dx = tap % 3 - 1;
                const int c7 = (dx + 1 + l15) & 7;
                const uint32_t rowb = sb + OFF_AS + (uint32_t)(wm + dy + 1) * ROWB
                                    + (uint32_t)(dx + 1 + l15) * 128;
                const uint32_t Bb = sb + OFF_B + (uint32_t)(ch % 4) * 16384 + Bwn;

                #pragma unroll
                for (int ks = 0; ks < 4; ks++) {
                    if (doA) {                       // phase = u*2 + ks/2
                        if ((ks & 1) == 0) {
                            winA = (u * 2 + (ks >> 1)) * 16 + w16;
                            fA = ldA1(xb, hinA, winA, tcc, q15);
                        } else {
                            stA1(sb + OFF_AS, srow, winA, q15, fA);
                        }
                    }
                    const uint32_t xo = (uint32_t)(((ks * 2 + kh) ^ c7) << 4);
                    uint32_t af[4][4];
                    #pragma unroll
                    for (int i = 0; i < 4; i++)
                        ldmA(af[i], rowb + i * 2048 + xo);
                    #pragma unroll
                    for (int j = 0; j < 2; j++) {
                        uint32_t bf[4];
                        lds128(bf, Bb + ks * 2048 + j * 512 + lane * 16);
                        #pragma unroll
                        for (int i = 0; i < 4; i++) {
                            mma_bf16(acc[i][2 * j],     af[i], bf[0], bf[1]);
                            mma_bf16(acc[i][2 * j + 1], af[i], bf[2], bf[3]);
                        }
                    }
                }
            }
        }
    }

    // ---- fused epilogue: bias + ReLU + 1x1 conv + sigmoid ----
    float psum[8];
    #pragma unroll
    for (int i = 0; i < 4; i++)
        #pragma unroll
        for (int rh = 0; rh < 2; rh++) {
            float s = 0.f;
            #pragma unroll
            for (int nt = 0; nt < 4; nt++) {
                const int n0 = wn * 32 + nt * 8 + 2 * t;
                s += fmaxf(acc[i][nt][rh * 2 + 0] + b1s[n0],     0.f) * w2s[n0];
                s += fmaxf(acc[i][nt][rh * 2 + 1] + b1s[n0 + 1], 0.f) * w2s[n0 + 1];
            }
            psum[i * 2 + rh] = s;
        }
    #pragma unroll
    for (int k = 0; k < 8; k++) {
        psum[k] += __shfl_xor_sync(0xffffffffu, psum[k], 1);
        psum[k] += __shfl_xor_sync(0xffffffffu, psum[k], 2);
    }
    __syncthreads();                                   // all A-reads done before reuse
    float* part = reinterpret_cast<float*>(smem + OFF_AS);
    if (t == 0) {
        #pragma unroll
        for (int i = 0; i < 4; i++)
            #pragma unroll
            for (int rh = 0; rh < 2; rh++) {
                const int m = wm * 64 + i * 16 + g + rh * 8;   // 0..127
                part[wn * 128 + m] = psum[i * 2 + rh];
            }
    }
    __syncthreads();
    if (tid < 128) {
        const float s = part[tid] + part[128 + tid] + part[256 + tid] + part[384 + tid] + b2[0];
        out[(size_t)blockIdx.x * 128 + tid] = 1.f / (1.f + __expf(-s));
    }
}

extern "C" void kernel_launch(void* const* d_in, const int* in_sizes, int n_in,
                              void* d_out, int out_size)
{
    const float* x  = (const float*)d_in[0];   // (32,64,64,384)
    const float* w1 = (const float*)d_in[1];   // (3,3,384,128) HWIO
    const float* b1 = (const float*)d_in[2];   // (128)
    const float* w2 = (const float*)d_in[3];   // (128)
    const float* b2 = (const float*)d_in[4];   // (1)
    float* out = (float*)d_out;                // (32,64,64,1)

    cudaFuncSetAttribute(kp_mma_kernel,
                         cudaFuncAttributeMaxDynamicSharedMemorySize, SMEM_TOTAL);

    prep_w1_kernel<<<216, 256>>>(w1);
    kp_mma_kernel<<<1024, THREADS, SMEM_TOTAL>>>(x, b1, w2, b2, out);
}

// round 9
// speedup vs baseline: 1.1480x; 1.1480x over previous
#include <cuda_runtime.h>
#include <cuda_bf16.h>
#include <cstdint>

#define B_    32
#define CIN   384
#define CHID  128
#define NCC   6
#define NTAPS 9
#define THREADS 256

// As layout: byte = srow*ROWB + col*128 + ((k8 ^ (col&7))<<4) + low8
#define ROWB     (66 * 128)               // 8448 bytes per halo row
#define AS_BYTES (4 * ROWB)               // 33792 (4 halo rows)

#define OFF_B1S 0
#define OFF_W2S 512
#define OFF_AS  1024
#define SMEM_TOTAL (OFF_AS + AS_BYTES)    // 34816

// W1 bf16 in mma-fragment order: [tap][cc][half][ks][jj][lane] x 16B
__device__ __align__(16) uint4 g_w1b[NTAPS * NCC * 2 * 4 * 4 * 32];

__device__ __forceinline__ uint32_t smem_u32(const void* p) {
    uint32_t a;
    asm("{ .reg .u64 t; cvta.to.shared.u64 t, %1; cvt.u32.u64 %0, t; }" : "=r"(a) : "l"(p));
    return a;
}
__device__ __forceinline__ uint32_t cvt2(float lo, float hi) {
    __nv_bfloat162 h = __float22bfloat162_rn(make_float2(lo, hi));
    return *reinterpret_cast<uint32_t*>(&h);
}
__device__ __forceinline__ void sts64(uint32_t a, uint32_t x, uint32_t y) {
    asm volatile("st.shared.v2.b32 [%0], {%1,%2};" :: "r"(a), "r"(x), "r"(y) : "memory");
}
__device__ __forceinline__ void sts128(uint32_t a, uint32_t x, uint32_t y, uint32_t z, uint32_t w) {
    asm volatile("st.shared.v4.b32 [%0], {%1,%2,%3,%4};" :: "r"(a), "r"(x), "r"(y), "r"(z), "r"(w) : "memory");
}
__device__ __forceinline__ void ldmA(uint32_t* r, uint32_t a) {
    asm volatile("ldmatrix.sync.aligned.m8n8.x4.shared.b16 {%0,%1,%2,%3}, [%4];"
                 : "=r"(r[0]), "=r"(r[1]), "=r"(r[2]), "=r"(r[3]) : "r"(a));
}
__device__ __forceinline__ void mma_bf16(float* d, const uint32_t* a, uint32_t b0, uint32_t b1) {
    asm volatile("mma.sync.aligned.m16n8k16.row.col.f32.bf16.bf16.f32 "
                 "{%0,%1,%2,%3}, {%4,%5,%6,%7}, {%8,%9}, {%0,%1,%2,%3};"
                 : "+f"(d[0]), "+f"(d[1]), "+f"(d[2]), "+f"(d[3])
                 : "r"(a[0]), "r"(a[1]), "r"(a[2]), "r"(a[3]), "r"(b0), "r"(b1));
}

// ---- prep: W1 (HWIO fp32) -> g_w1b (bf16, mma-fragment order) ----
__global__ void prep_w1_kernel(const float* __restrict__ w1) {
    int u = blockIdx.x * 256 + threadIdx.x;          // 0..55295
    int lane = u & 31;  int r = u >> 5;
    int j    = r & 3;   r >>= 2;
    int ks   = r & 3;   r >>= 2;
    int half = r & 1;   r >>= 1;
    int cc   = r % NCC;
    int tap  = r / NCC;
    int g = lane >> 2, t = lane & 3;
    uint32_t wd[4];
    #pragma unroll
    for (int w = 0; w < 4; w++) {
        int nt = 2 * j + (w >> 1);
        int n  = half * 64 + nt * 8 + g;
        int kb = cc * 64 + ks * 16 + 2 * t + (w & 1) * 8;
        float f0 = w1[(size_t)(tap * CIN + kb) * CHID + n];
        float f1 = w1[(size_t)(tap * CIN + kb + 1) * CHID + n];
        wd[w] = cvt2(f0, f1);
    }
    g_w1b[u] = make_uint4(wd[0], wd[1], wd[2], wd[3]);
}

// ---- canonical A staging for one cc chunk: 4 halo rows x 64 cols x 64 ch ----
__device__ __forceinline__ void stageA_cc(const float* __restrict__ x, uint32_t abase,
                                          int b, int rp, int cc, int tid) {
    const int r0 = rp * 2 - 1;
    #pragma unroll
    for (int it = 0; it < 16; it++) {
        const int j    = it * THREADS + tid;      // 0..4095
        const int q    = j & 15;                  // float4 index (4 ch)
        const int win  = (j >> 4) & 63;
        const int srow = j >> 10;                 // 0..3
        const int hin  = r0 + srow;
        if ((unsigned)hin < 64u) {
            const float4 f = *reinterpret_cast<const float4*>(
                x + ((size_t)((b * 64 + hin) * 64 + win)) * CIN + cc * 64 + q * 4);
            const int sc = win + 1;
            const uint32_t addr = abase + srow * ROWB + sc * 128 +
                                  (((q >> 1) ^ (sc & 7)) << 4) + (q & 1) * 8;
            sts64(addr, cvt2(f.x, f.y), cvt2(f.z, f.w));
        }
    }
}

__global__ void __launch_bounds__(THREADS, 2)
kp_mma_kernel(const float* __restrict__ x,
              const float* __restrict__ b1,
              const float* __restrict__ w2,
              const float* __restrict__ b2,
              float* __restrict__ out)
{
    extern __shared__ char smem[];
    const uint32_t sb = smem_u32(smem);
    const int tid  = threadIdx.x;
    const int wid  = tid >> 5;
    const int lane = tid & 31;
    const int wm   = wid >> 2;      // 0..1: output row rp*2+wm
    const int wn   = wid & 3;       // 0..3: n-slice of 32
    const int g    = lane >> 2;
    const int t    = lane & 3;
    const int l15  = lane & 15;
    const int kh   = lane >> 4;     // ldmatrix k-half

    const int b  = blockIdx.x >> 5;
    const int rp = blockIdx.x & 31;

    float* b1s = reinterpret_cast<float*>(smem + OFF_B1S);
    float* w2s = reinterpret_cast<float*>(smem + OFF_W2S);
    if (tid < CHID) { b1s[tid] = b1[tid]; w2s[tid] = w2[tid]; }

    // zero As once: halo columns (sc=0,65) and out-of-image rows stay 0
    #pragma unroll
    for (int i = 0; i < 9; i++) {
        const int idx = i * THREADS + tid;
        if (idx < AS_BYTES / 16)
            sts128(sb + OFF_AS + idx * 16, 0u, 0u, 0u, 0u);
    }

    float acc[4][4][4];
    #pragma unroll
    for (int i = 0; i < 4; i++)
        #pragma unroll
        for (int nt = 0; nt < 4; nt++)
            #pragma unroll
            for (int c = 0; c < 4; c++) acc[i][nt][c] = 0.f;

    // B fragment base for this warp+lane (uint4 units):
    // byte off within chunk = (wn>>1)*8192 + (wn&1)*1024 + ks*2048 + j*512 + lane*16
    const uint4* __restrict__ bw =
        g_w1b + ((wn >> 1) * 512 + (wn & 1) * 64 + lane);

    for (int cc = 0; cc < NCC; cc++) {
        __syncthreads();                       // previous-cc A readers done
        stageA_cc(x, sb + OFF_AS, b, rp, cc, tid);
        __syncthreads();                       // A visible to all warps

        #pragma unroll
        for (int tap = 0; tap < NTAPS; tap++) {
            const int dy = tap / 3 - 1, dx = tap % 3 - 1;
            const int c7 = (dx + 1 + l15) & 7;
            const uint32_t rowb = sb + OFF_AS + (uint32_t)(wm + dy + 1) * ROWB
                                + (uint32_t)(dx + 1 + l15) * 128;
            const uint4* __restrict__ bc = bw + (size_t)(tap * NCC + cc) * 1024;

            #pragma unroll
            for (int ks = 0; ks < 4; ks++) {
                const uint32_t xo = (uint32_t)(((ks * 2 + kh) ^ c7) << 4);
                uint32_t af[4][4];
                #pragma unroll
                for (int i = 0; i < 4; i++)
                    ldmA(af[i], rowb + i * 2048 + xo);
                #pragma unroll
                for (int j = 0; j < 2; j++) {
                    const uint4 bf = __ldg(bc + ks * 128 + j * 32);
                    #pragma unroll
                    for (int i = 0; i < 4; i++) {
                        mma_bf16(acc[i][2 * j],     af[i], bf.x, bf.y);
                        mma_bf16(acc[i][2 * j + 1], af[i], bf.z, bf.w);
                    }
                }
            }
        }
    }

    // ---- fused epilogue: bias + ReLU + 1x1 conv + sigmoid ----
    float psum[8];
    #pragma unroll
    for (int i = 0; i < 4; i++)
        #pragma unroll
        for (int rh = 0; rh < 2; rh++) {
            float s = 0.f;
            #pragma unroll
            for (int nt = 0; nt < 4; nt++) {
                const int n0 = wn * 32 + nt * 8 + 2 * t;
                s += fmaxf(acc[i][nt][rh * 2 + 0] + b1s[n0],     0.f) * w2s[n0];
                s += fmaxf(acc[i][nt][rh * 2 + 1] + b1s[n0 + 1], 0.f) * w2s[n0 + 1];
            }
            psum[i * 2 + rh] = s;
        }
    #pragma unroll
    for (int k = 0; k < 8; k++) {
        psum[k] += __shfl_xor_sync(0xffffffffu, psum[k], 1);
        psum[k] += __shfl_xor_sync(0xffffffffu, psum[k], 2);
    }
    __syncthreads();                                   // all A-reads done before reuse
    float* part = reinterpret_cast<float*>(smem + OFF_AS);
    if (t == 0) {
        #pragma unroll
        for (int i = 0; i < 4; i++)
            #pragma unroll
            for (int rh = 0; rh < 2; rh++) {
                const int m = wm * 64 + i * 16 + g + rh * 8;   // 0..127
                part[wn * 128 + m] = psum[i * 2 + rh];
            }
    }
    __syncthreads();
    if (tid < 128) {
        const float s = part[tid] + part[128 + tid] + part[256 + tid] + part[384 + tid] + b2[0];
        out[(size_t)blockIdx.x * 128 + tid] = 1.f / (1.f + __expf(-s));
    }
}

extern "C" void kernel_launch(void* const* d_in, const int* in_sizes, int n_in,
                              void* d_out, int out_size)
{
    const float* x  = (const float*)d_in[0];   // (32,64,64,384)
    const float* w1 = (const float*)d_in[1];   // (3,3,384,128) HWIO
    const float* b1 = (const float*)d_in[2];   // (128)
    const float* w2 = (const float*)d_in[3];   // (128)
    const float* b2 = (const float*)d_in[4];   // (1)
    float* out = (float*)d_out;                // (32,64,64,1)

    cudaFuncSetAttribute(kp_mma_kernel,
                         cudaFuncAttributeMaxDynamicSharedMemorySize, SMEM_TOTAL);

    prep_w1_kernel<<<216, 256>>>(w1);
    kp_mma_kernel<<<1024, THREADS, SMEM_TOTAL>>>(x, b1, w2, b2, out);
}

// round 10
// speedup vs baseline: 1.1694x; 1.0187x over previous
#include <cuda_runtime.h>
#include <cuda_bf16.h>
#include <cstdint>

#define B_    32
#define CIN   384
#define CHID  128
#define NCC   6
#define NTAPS 9
#define THREADS 256

// As layout: byte = srow*ROWB + col*128 + ((k8 ^ (col&7))<<4) + low8
#define ROWB     (66 * 128)               // 8448 bytes per halo row
#define AS_BYTES (4 * ROWB)               // 33792 (4 halo rows)

#define OFF_B1S 0
#define OFF_W2S 512
#define OFF_AS  1024
#define OFF_XF  (OFF_AS + AS_BYTES)       // 34816: fp32 staging, 4*64*64ch*4B
#define XF_BYTES 65536
#define SMEM_TOTAL (OFF_XF + XF_BYTES)    // 100352

// W1 bf16 in mma-fragment order: [tap][cc][half][ks][jj][lane] x 16B
__device__ __align__(16) uint4 g_w1b[NTAPS * NCC * 2 * 4 * 4 * 32];

__device__ __forceinline__ uint32_t smem_u32(const void* p) {
    uint32_t a;
    asm("{ .reg .u64 t; cvta.to.shared.u64 t, %1; cvt.u32.u64 %0, t; }" : "=r"(a) : "l"(p));
    return a;
}
__device__ __forceinline__ uint32_t cvt2(float lo, float hi) {
    __nv_bfloat162 h = __float22bfloat162_rn(make_float2(lo, hi));
    return *reinterpret_cast<uint32_t*>(&h);
}
__device__ __forceinline__ void sts64(uint32_t a, uint32_t x, uint32_t y) {
    asm volatile("st.shared.v2.b32 [%0], {%1,%2};" :: "r"(a), "r"(x), "r"(y) : "memory");
}
__device__ __forceinline__ void sts128(uint32_t a, uint32_t x, uint32_t y, uint32_t z, uint32_t w) {
    asm volatile("st.shared.v4.b32 [%0], {%1,%2,%3,%4};" :: "r"(a), "r"(x), "r"(y), "r"(z), "r"(w) : "memory");
}
__device__ __forceinline__ void lds128f(float4* f, uint32_t a) {
    asm volatile("ld.shared.v4.f32 {%0,%1,%2,%3}, [%4];"
                 : "=f"(f->x), "=f"(f->y), "=f"(f->z), "=f"(f->w) : "r"(a));
}
__device__ __forceinline__ void ldmA(uint32_t* r, uint32_t a) {
    asm volatile("ldmatrix.sync.aligned.m8n8.x4.shared.b16 {%0,%1,%2,%3}, [%4];"
                 : "=r"(r[0]), "=r"(r[1]), "=r"(r[2]), "=r"(r[3]) : "r"(a));
}
__device__ __forceinline__ void mma_bf16(float* d, const uint32_t* a, uint32_t b0, uint32_t b1) {
    asm volatile("mma.sync.aligned.m16n8k16.row.col.f32.bf16.bf16.f32 "
                 "{%0,%1,%2,%3}, {%4,%5,%6,%7}, {%8,%9}, {%0,%1,%2,%3};"
                 : "+f"(d[0]), "+f"(d[1]), "+f"(d[2]), "+f"(d[3])
                 : "r"(a[0]), "r"(a[1]), "r"(a[2]), "r"(a[3]), "r"(b0), "r"(b1));
}

// ---- prep: W1 (HWIO fp32) -> g_w1b (bf16, mma-fragment order) ----
__global__ void prep_w1_kernel(const float* __restrict__ w1) {
    int u = blockIdx.x * 256 + threadIdx.x;          // 0..55295
    int lane = u & 31;  int r = u >> 5;
    int j    = r & 3;   r >>= 2;
    int ks   = r & 3;   r >>= 2;
    int half = r & 1;   r >>= 1;
    int cc   = r % NCC;
    int tap  = r / NCC;
    int g = lane >> 2, t = lane & 3;
    uint32_t wd[4];
    #pragma unroll
    for (int w = 0; w < 4; w++) {
        int nt = 2 * j + (w >> 1);
        int n  = half * 64 + nt * 8 + g;
        int kb = cc * 64 + ks * 16 + 2 * t + (w & 1) * 8;
        float f0 = w1[(size_t)(tap * CIN + kb) * CHID + n];
        float f1 = w1[(size_t)(tap * CIN + kb + 1) * CHID + n];
        wd[w] = cvt2(f0, f1);
    }
    g_w1b[u] = make_uint4(wd[0], wd[1], wd[2], wd[3]);
}

// ---- cp.async prefetch of one cc's raw fp32 x-tile into XF ----
// XF float4 index j = srow*1024 + win*16 + q  (j = it*256 + tid)
__device__ __forceinline__ void prefetchX(const float* __restrict__ xb, uint32_t xfbase,
                                          int rp, int cc, int tid) {
    const int r0 = rp * 2 - 1;
    #pragma unroll
    for (int it = 0; it < 16; it++) {
        const int j    = it * THREADS + tid;
        const int q    = j & 15;
        const int win  = (j >> 4) & 63;
        const int srow = j >> 10;
        const int hin  = r0 + srow;
        const bool ok  = (unsigned)hin < 64u;
        const int hc   = ok ? hin : 0;                 // safe address
        const uint32_t ssz = ok ? 16u : 0u;            // 0 -> zero-fill
        size_t ga = (size_t)__cvta_generic_to_global(
            xb + ((size_t)(hc * 64 + win)) * CIN + cc * 64 + q * 4);
        asm volatile("cp.async.cg.shared.global [%0], [%1], 16, %2;"
                     :: "r"(xfbase + (uint32_t)j * 16), "l"(ga), "r"(ssz) : "memory");
    }
}

// ---- restage: XF (fp32 smem) -> As (bf16 swizzled) ----
__device__ __forceinline__ void restageA(uint32_t xfbase, uint32_t abase, int tid) {
    #pragma unroll
    for (int it = 0; it < 16; it++) {
        const int j    = it * THREADS + tid;
        const int q    = j & 15;
        const int win  = (j >> 4) & 63;
        const int srow = j >> 10;
        float4 f;
        lds128f(&f, xfbase + (uint32_t)j * 16);
        const int sc = win + 1;
        const uint32_t addr = abase + srow * ROWB + sc * 128 +
                              (((q >> 1) ^ (sc & 7)) << 4) + (q & 1) * 8;
        sts64(addr, cvt2(f.x, f.y), cvt2(f.z, f.w));
    }
}

__global__ void __launch_bounds__(THREADS, 2)
kp_mma_kernel(const float* __restrict__ x,
              const float* __restrict__ b1,
              const float* __restrict__ w2,
              const float* __restrict__ b2,
              float* __restrict__ out)
{
    extern __shared__ char smem[];
    const uint32_t sb = smem_u32(smem);
    const int tid  = threadIdx.x;
    const int lane = tid & 31;
    const int wid  = tid >> 5;
    const int wm   = wid >> 2;      // 0..1: output row rp*2+wm
    const int wn   = wid & 3;       // 0..3: n-slice of 32
    const int g    = lane >> 2;
    const int t    = lane & 3;
    const int l15  = lane & 15;
    const int kh   = lane >> 4;     // ldmatrix k-half

    const int b  = blockIdx.x >> 5;
    const int rp = blockIdx.x & 31;
    const float* xb = x + (size_t)b * 64 * 64 * CIN;

    // prologue: cc=0 x-tile prefetch in flight ASAP
    prefetchX(xb, sb + OFF_XF, rp, 0, tid);
    asm volatile("cp.async.commit_group;" ::: "memory");

    float* b1s = reinterpret_cast<float*>(smem + OFF_B1S);
    float* w2s = reinterpret_cast<float*>(smem + OFF_W2S);
    if (tid < CHID) { b1s[tid] = b1[tid]; w2s[tid] = w2[tid]; }

    // zero As once: halo columns (sc=0,65) stay 0 forever
    #pragma unroll
    for (int i = 0; i < 9; i++) {
        const int idx = i * THREADS + tid;
        if (idx < AS_BYTES / 16)
            sts128(sb + OFF_AS + idx * 16, 0u, 0u, 0u, 0u);
    }

    float acc[4][4][4];
    #pragma unroll
    for (int i = 0; i < 4; i++)
        #pragma unroll
        for (int nt = 0; nt < 4; nt++)
            #pragma unroll
            for (int c = 0; c < 4; c++) acc[i][nt][c] = 0.f;

    // B fragment base for this warp+lane (uint4 units)
    const uint4* __restrict__ bw =
        g_w1b + ((wn >> 1) * 512 + (wn & 1) * 64 + lane);

    for (int cc = 0; cc < NCC; cc++) {
        asm volatile("cp.async.wait_group 0;" ::: "memory");
        __syncthreads();               // XF ready everywhere + prev-cc A readers done
        restageA(sb + OFF_XF, sb + OFF_AS, tid);
        __syncthreads();               // A visible; XF reads complete

        if (cc + 1 < NCC) {            // prefetch next cc under this cc's MMAs
            prefetchX(xb, sb + OFF_XF, rp, cc + 1, tid);
            asm volatile("cp.async.commit_group;" ::: "memory");
        }

        #pragma unroll
        for (int tap = 0; tap < NTAPS; tap++) {
            const int dy = tap / 3 - 1, dx = tap % 3 - 1;
            const int c7 = (dx + 1 + l15) & 7;
            const uint32_t rowb = sb + OFF_AS + (uint32_t)(wm + dy + 1) * ROWB
                                + (uint32_t)(dx + 1 + l15) * 128;
            const uint4* __restrict__ bc = bw + (size_t)(tap * NCC + cc) * 1024;

            #pragma unroll
            for (int ks = 0; ks < 4; ks++) {
                const uint32_t xo = (uint32_t)(((ks * 2 + kh) ^ c7) << 4);
                uint32_t af[4][4];
                #pragma unroll
                for (int i = 0; i < 4; i++)
                    ldmA(af[i], rowb + i * 2048 + xo);
                #pragma unroll
                for (int j = 0; j < 2; j++) {
                    const uint4 bf = __ldg(bc + ks * 128 + j * 32);
                    #pragma unroll
                    for (int i = 0; i < 4; i++) {
                        mma_bf16(acc[i][2 * j],     af[i], bf.x, bf.y);
                        mma_bf16(acc[i][2 * j + 1], af[i], bf.z, bf.w);
                    }
                }
            }
        }
    }

    // ---- fused epilogue: bias + ReLU + 1x1 conv + sigmoid ----
    float psum[8];
    #pragma unroll
    for (int i = 0; i < 4; i++)
        #pragma unroll
        for (int rh = 0; rh < 2; rh++) {
            float s = 0.f;
            #pragma unroll
            for (int nt = 0; nt < 4; nt++) {
                const int n0 = wn * 32 + nt * 8 + 2 * t;
                s += fmaxf(acc[i][nt][rh * 2 + 0] + b1s[n0],     0.f) * w2s[n0];
                s += fmaxf(acc[i][nt][rh * 2 + 1] + b1s[n0 + 1], 0.f) * w2s[n0 + 1];
            }
            psum[i * 2 + rh] = s;
        }
    #pragma unroll
    for (int k = 0; k < 8; k++) {
        psum[k] += __shfl_xor_sync(0xffffffffu, psum[k], 1);
        psum[k] += __shfl_xor_sync(0xffffffffu, psum[k], 2);
    }
    __syncthreads();                                   // all A-reads done before reuse
    float* part = reinterpret_cast<float*>(smem + OFF_AS);
    if (t == 0) {
        #pragma unroll
        for (int i = 0; i < 4; i++)
            #pragma unroll
            for (int rh = 0; rh < 2; rh++) {
                const int m = wm * 64 + i * 16 + g + rh * 8;   // 0..127
                part[wn * 128 + m] = psum[i * 2 + rh];
            }
    }
    __syncthreads();
    if (tid < 128) {
        const float s = part[tid] + part[128 + tid] + part[256 + tid] + part[384 + tid] + b2[0];
        out[(size_t)blockIdx.x * 128 + tid] = 1.f / (1.f + __expf(-s));
    }
}

extern "C" void kernel_launch(void* const* d_in, const int* in_sizes, int n_in,
                              void* d_out, int out_size)
{
    const float* x  = (const float*)d_in[0];   // (32,64,64,384)
    const float* w1 = (const float*)d_in[1];   // (3,3,384,128) HWIO
    const float* b1 = (const float*)d_in[2];   // (128)
    const float* w2 = (const float*)d_in[3];   // (128)
    const float* b2 = (const float*)d_in[4];   // (1)
    float* out = (float*)d_out;                // (32,64,64,1)

    cudaFuncSetAttribute(kp_mma_kernel,
                         cudaFuncAttributeMaxDynamicSharedMemorySize, SMEM_TOTAL);

    prep_w1_kernel<<<216, 256>>>(w1);
    kp_mma_kernel<<<1024, THREADS, SMEM_TOTAL>>>(x, b1, w2, b2, out);
}